// round 3
// baseline (speedup 1.0000x reference)
#include <cuda_runtime.h>
#include <cstdint>

#define SEQ   2048
#define BATCH 2
#define EMB   1024
#define NH    16
#define DH    64
#define MROWS (SEQ * BATCH)  // 4096

static const size_t OUT_ELEMS  = (size_t)MROWS * EMB;            // 4,194,304
static const size_t ATTN_ELEMS = (size_t)BATCH * NH * SEQ * SEQ; // 134,217,728

// Scratch (allocation-free rule: __device__ globals)
__device__ float g_Q[BATCH * NH * SEQ * DH];   // (b,h,n,dh), scale folded in
__device__ float g_K[BATCH * NH * SEQ * DH];
__device__ float g_V[BATCH * NH * SEQ * DH];
__device__ float g_O[MROWS * EMB];             // (n,b,e) layout
__device__ float g_S[BATCH * NH * SEQ * SEQ];  // attn fallback scratch
__device__ float g_OUT_FB[MROWS * EMB];        // out fallback scratch

__device__ __forceinline__ uint32_t f2tf(float x) {
    uint32_t r;
    asm("cvt.rna.tf32.f32 %0, %1;" : "=r"(r) : "f"(x));
    return r;
}

__device__ __forceinline__ void mma8(float* c, const uint32_t* a, const uint32_t* b) {
    asm volatile(
        "mma.sync.aligned.m16n8k8.row.col.f32.tf32.tf32.f32 "
        "{%0,%1,%2,%3}, {%4,%5,%6,%7}, {%8,%9}, {%0,%1,%2,%3};\n"
        : "+f"(c[0]), "+f"(c[1]), "+f"(c[2]), "+f"(c[3])
        : "r"(a[0]), "r"(a[1]), "r"(a[2]), "r"(a[3]), "r"(b[0]), "r"(b[1]));
}

// ---------------------------------------------------------------------------
// TF32 GEMM, C[M,N] = A[M,K] * B[N,K]^T, M=4096, N=K=1024.
// Block tile 128x128, K staged 16. 8 warps: warp grid 2(m) x 4(n), warp 64x32.
// DEST 0/1/2: scatter to g_Q/g_K/g_V (b,h,n,dh) with scale.
// DEST 3:     A = g_O, out = row-major + bias.
// __launch_bounds__(256,2): cap regs at 128 so 2 CTAs/SM (R2 showed occ 12.4%).
// ---------------------------------------------------------------------------
template <int DEST>
__global__ __launch_bounds__(256, 2) void gemm_tf32(const float* __restrict__ A_ext,
                                                    const float* __restrict__ Bm,
                                                    const float* __restrict__ bias,
                                                    float scale,
                                                    float* __restrict__ out_ext,
                                                    int out_is_fb)
{
    __shared__ uint32_t As[2][16][132];
    __shared__ uint32_t Bs[2][16][132];

    const float* A = (DEST == 3) ? (const float*)g_O : A_ext;
    const int K = EMB;
    const int bm = blockIdx.y * 128;
    const int bn = blockIdx.x * 128;
    const int tid = threadIdx.x;
    const int lrow = tid >> 1;
    const int lk = (tid & 1) * 8;
    const int w = tid >> 5;
    const int lane = tid & 31;
    const int wm = (w & 1) * 64;
    const int wn = (w >> 1) * 32;
    const int grp = lane >> 2;
    const int tig = lane & 3;

    float c[4][4][4];
#pragma unroll
    for (int mt = 0; mt < 4; ++mt)
#pragma unroll
        for (int nt = 0; nt < 4; ++nt)
#pragma unroll
            for (int i = 0; i < 4; ++i) c[mt][nt][i] = 0.0f;

    const float* pa = A + (size_t)(bm + lrow) * K + lk;
    const float* pb = Bm + (size_t)(bn + lrow) * K + lk;

    float4 ra0 = *(const float4*)pa;
    float4 ra1 = *(const float4*)(pa + 4);
    float4 rb0 = *(const float4*)pb;
    float4 rb1 = *(const float4*)(pb + 4);

    As[0][lk + 0][lrow] = f2tf(ra0.x); As[0][lk + 1][lrow] = f2tf(ra0.y);
    As[0][lk + 2][lrow] = f2tf(ra0.z); As[0][lk + 3][lrow] = f2tf(ra0.w);
    As[0][lk + 4][lrow] = f2tf(ra1.x); As[0][lk + 5][lrow] = f2tf(ra1.y);
    As[0][lk + 6][lrow] = f2tf(ra1.z); As[0][lk + 7][lrow] = f2tf(ra1.w);
    Bs[0][lk + 0][lrow] = f2tf(rb0.x); Bs[0][lk + 1][lrow] = f2tf(rb0.y);
    Bs[0][lk + 2][lrow] = f2tf(rb0.z); Bs[0][lk + 3][lrow] = f2tf(rb0.w);
    Bs[0][lk + 4][lrow] = f2tf(rb1.x); Bs[0][lk + 5][lrow] = f2tf(rb1.y);
    Bs[0][lk + 6][lrow] = f2tf(rb1.z); Bs[0][lk + 7][lrow] = f2tf(rb1.w);
    __syncthreads();

    const int nk = K / 16;
    for (int kt = 0; kt < nk; ++kt) {
        const int buf = kt & 1;
        if (kt + 1 < nk) {
            const float* qa = pa + (kt + 1) * 16;
            ra0 = *(const float4*)qa; ra1 = *(const float4*)(qa + 4);
            const float* qb = pb + (kt + 1) * 16;
            rb0 = *(const float4*)qb; rb1 = *(const float4*)(qb + 4);
        }
#pragma unroll
        for (int ks = 0; ks < 16; ks += 8) {
            uint32_t af[4][4], bf[4][2];
#pragma unroll
            for (int mt = 0; mt < 4; ++mt) {
                int m0 = wm + mt * 16 + grp;
                af[mt][0] = As[buf][ks + tig][m0];
                af[mt][1] = As[buf][ks + tig][m0 + 8];
                af[mt][2] = As[buf][ks + tig + 4][m0];
                af[mt][3] = As[buf][ks + tig + 4][m0 + 8];
            }
#pragma unroll
            for (int nt = 0; nt < 4; ++nt) {
                int n0 = wn + nt * 8 + grp;
                bf[nt][0] = Bs[buf][ks + tig][n0];
                bf[nt][1] = Bs[buf][ks + tig + 4][n0];
            }
#pragma unroll
            for (int mt = 0; mt < 4; ++mt)
#pragma unroll
                for (int nt = 0; nt < 4; ++nt)
                    mma8(c[mt][nt], af[mt], bf[nt]);
        }
        if (kt + 1 < nk) {
            const int nb = buf ^ 1;
            As[nb][lk + 0][lrow] = f2tf(ra0.x); As[nb][lk + 1][lrow] = f2tf(ra0.y);
            As[nb][lk + 2][lrow] = f2tf(ra0.z); As[nb][lk + 3][lrow] = f2tf(ra0.w);
            As[nb][lk + 4][lrow] = f2tf(ra1.x); As[nb][lk + 5][lrow] = f2tf(ra1.y);
            As[nb][lk + 6][lrow] = f2tf(ra1.z); As[nb][lk + 7][lrow] = f2tf(ra1.w);
            Bs[nb][lk + 0][lrow] = f2tf(rb0.x); Bs[nb][lk + 1][lrow] = f2tf(rb0.y);
            Bs[nb][lk + 2][lrow] = f2tf(rb0.z); Bs[nb][lk + 3][lrow] = f2tf(rb0.w);
            Bs[nb][lk + 4][lrow] = f2tf(rb1.x); Bs[nb][lk + 5][lrow] = f2tf(rb1.y);
            Bs[nb][lk + 6][lrow] = f2tf(rb1.z); Bs[nb][lk + 7][lrow] = f2tf(rb1.w);
        }
        __syncthreads();
    }

    float* out3 = (DEST == 3) ? (out_is_fb ? (float*)g_OUT_FB : out_ext) : (float*)nullptr;
    float* dst = (DEST == 0) ? g_Q : (DEST == 1) ? g_K : (DEST == 2) ? g_V : (float*)nullptr;

#pragma unroll
    for (int mt = 0; mt < 4; ++mt) {
#pragma unroll
        for (int nt = 0; nt < 4; ++nt) {
            const int e = bn + wn + nt * 8 + 2 * tig;
#pragma unroll
            for (int h2 = 0; h2 < 2; ++h2) {
                const int m = bm + wm + mt * 16 + grp + h2 * 8;
                float2 v = make_float2(c[mt][nt][h2 * 2 + 0] * scale,
                                       c[mt][nt][h2 * 2 + 1] * scale);
                if (DEST <= 2) {
                    int n_ = m >> 1;  // BATCH == 2
                    int bb = m & 1;
                    int hh = e >> 6;  // DH == 64
                    int dh = e & 63;
                    *(float2*)(dst + (((size_t)(bb * NH + hh) * SEQ + n_) * DH + dh)) = v;
                } else {
                    v.x += bias[e];
                    v.y += bias[e + 1];
                    *(float2*)(out3 + (size_t)m * EMB + e) = v;
                }
            }
        }
    }
}

// ---------------------------------------------------------------------------
// Fused attention: per block = one (b,h) and 16 query rows.
//   Phase 1: S[16][2048] = Q K^T into SMEM (tf32 mma; Q a-frags in registers,
//            K streamed 64 rows at a time, double-buffered).
//   Phase 2: row max -> exp (stored back as tf32 bits) -> row sum;
//            write normalized attn to global ONCE.
//   Phase 3: O[16][64] = (exp S) V via tf32 mma (V streamed), scaled by
//            1/rowsum in the epilogue; cross-warp partials reduced in SMEM.
// SMEM: Ssm 16x2052 fp32 (131328B) + KV 2x64x68 u32 (34816B, reused as Osm)
//       + stats (640B) = 166784B dynamic.
// ---------------------------------------------------------------------------
#define S_STRIDE 2052
#define KV_OFF   131328
#define ST_OFF   166144
#define FUSED_SMEM 166784

__global__ __launch_bounds__(256) void fused_attn(float* __restrict__ attn_ext,
                                                  int attn_is_scratch)
{
    extern __shared__ unsigned char smraw[];
    float* Ssm = (float*)smraw;                      // [16][2052]
    uint32_t* KV = (uint32_t*)(smraw + KV_OFF);      // [2][64*68]
    float* Wmax = (float*)(smraw + ST_OFF);          // [8][16]
    float* Rmax = Wmax + 128;                        // [16]
    float* Rsum = Wmax + 144;                        // [16] (stores 1/sum)

    float* Aout = attn_is_scratch ? (float*)g_S : attn_ext;
    const int bh = blockIdx.y;
    const int m0 = blockIdx.x * 16;
    const float* Qb = g_Q + ((size_t)bh * SEQ + m0) * DH;
    const float* Kb = g_K + (size_t)bh * SEQ * DH;
    const float* Vb = g_V + (size_t)bh * SEQ * DH;

    const int tid = threadIdx.x;
    const int w = tid >> 5;
    const int lane = tid & 31;
    const int g = lane >> 2;
    const int t = lane & 3;

    // loader mapping for 64x64-float chunks: 4 float4 per thread
    const int lrow0 = tid >> 4;          // fid = tid + j*256 -> row = fid>>4
    const int lc4 = (tid & 15) * 4;      // col within row

    // ---- Q a-fragments, entirely in registers (16x64 tile) ----
    uint32_t qa[8][4];
    {
        const float* q0 = Qb + (size_t)g * DH;
        const float* q1 = Qb + (size_t)(g + 8) * DH;
#pragma unroll
        for (int ks = 0; ks < 8; ++ks) {
            qa[ks][0] = f2tf(q0[ks * 8 + t]);
            qa[ks][1] = f2tf(q1[ks * 8 + t]);
            qa[ks][2] = f2tf(q0[ks * 8 + t + 4]);
            qa[ks][3] = f2tf(q1[ks * 8 + t + 4]);
        }
    }

    float rm0 = -1e30f, rm1 = -1e30f;
    float4 pf[4];

    // ---- Phase 1: QK^T ----
#pragma unroll
    for (int j = 0; j < 4; ++j)
        pf[j] = *(const float4*)(Kb + (size_t)(lrow0 + j * 16) * DH + lc4);
#pragma unroll
    for (int j = 0; j < 4; ++j) {
        uint4 u = make_uint4(f2tf(pf[j].x), f2tf(pf[j].y), f2tf(pf[j].z), f2tf(pf[j].w));
        *(uint4*)(KV + (lrow0 + j * 16) * 68 + lc4) = u;
    }
    __syncthreads();

    for (int c = 0; c < 32; ++c) {
        const int buf = c & 1;
        if (c < 31) {
#pragma unroll
            for (int j = 0; j < 4; ++j)
                pf[j] = *(const float4*)(Kb + (size_t)((c + 1) * 64 + lrow0 + j * 16) * DH + lc4);
        }
        const uint32_t* Kc = KV + buf * (64 * 68);
        const int nrow = w * 8 + g;
        float acc[4] = {0.f, 0.f, 0.f, 0.f};
#pragma unroll
        for (int ks = 0; ks < 8; ++ks) {
            uint32_t b[2];
            b[0] = Kc[nrow * 68 + ks * 8 + t];
            b[1] = Kc[nrow * 68 + ks * 8 + t + 4];
            mma8(acc, qa[ks], b);
        }
        const int col = c * 64 + w * 8 + 2 * t;
        Ssm[g * S_STRIDE + col] = acc[0];
        Ssm[g * S_STRIDE + col + 1] = acc[1];
        Ssm[(g + 8) * S_STRIDE + col] = acc[2];
        Ssm[(g + 8) * S_STRIDE + col + 1] = acc[3];
        rm0 = fmaxf(rm0, fmaxf(acc[0], acc[1]));
        rm1 = fmaxf(rm1, fmaxf(acc[2], acc[3]));
        if (c < 31) {
            uint32_t* Kn = KV + (buf ^ 1) * (64 * 68);
#pragma unroll
            for (int j = 0; j < 4; ++j) {
                uint4 u = make_uint4(f2tf(pf[j].x), f2tf(pf[j].y), f2tf(pf[j].z), f2tf(pf[j].w));
                *(uint4*)(Kn + (lrow0 + j * 16) * 68 + lc4) = u;
            }
        }
        __syncthreads();
    }

    // ---- row max reduction ----
    rm0 = fmaxf(rm0, __shfl_xor_sync(0xffffffffu, rm0, 1));
    rm0 = fmaxf(rm0, __shfl_xor_sync(0xffffffffu, rm0, 2));
    rm1 = fmaxf(rm1, __shfl_xor_sync(0xffffffffu, rm1, 1));
    rm1 = fmaxf(rm1, __shfl_xor_sync(0xffffffffu, rm1, 2));
    if (t == 0) {
        Wmax[w * 16 + g] = rm0;
        Wmax[w * 16 + 8 + g] = rm1;
    }
    __syncthreads();
    if (tid < 16) {
        float m = Wmax[tid];
#pragma unroll
        for (int ww = 1; ww < 8; ++ww) m = fmaxf(m, Wmax[ww * 16 + tid]);
        Rmax[tid] = m;
    }
    __syncthreads();

    // ---- Pass A: exp + row sum (store exp back as tf32 bits) ----
#pragma unroll
    for (int rr = 0; rr < 2; ++rr) {
        const int r = w + rr * 8;
        const float mx = Rmax[r];
        float* row = Ssm + (size_t)r * S_STRIDE;
        float s = 0.f;
#pragma unroll
        for (int i = 0; i < 16; ++i) {
            float4 v = *(float4*)(row + lane * 4 + i * 128);
            v.x = __expf(v.x - mx); v.y = __expf(v.y - mx);
            v.z = __expf(v.z - mx); v.w = __expf(v.w - mx);
            s += v.x + v.y + v.z + v.w;
            float4 o;
            o.x = __uint_as_float(f2tf(v.x)); o.y = __uint_as_float(f2tf(v.y));
            o.z = __uint_as_float(f2tf(v.z)); o.w = __uint_as_float(f2tf(v.w));
            *(float4*)(row + lane * 4 + i * 128) = o;
        }
#pragma unroll
        for (int o2 = 16; o2; o2 >>= 1) s += __shfl_xor_sync(0xffffffffu, s, o2);
        if (lane == 0) Rsum[r] = 1.0f / s;
    }
    __syncthreads();

    // ---- Pass B: write normalized attn to global (single DRAM write) ----
    {
        float* obase = Aout + ((size_t)bh * SEQ + m0) * SEQ;
#pragma unroll
        for (int rr = 0; rr < 2; ++rr) {
            const int r = w + rr * 8;
            const float inv = Rsum[r];
            const float* row = Ssm + (size_t)r * S_STRIDE;
            float* orow = obase + (size_t)r * SEQ;
#pragma unroll
            for (int i = 0; i < 16; ++i) {
                float4 v = *(const float4*)(row + lane * 4 + i * 128);
                v.x *= inv; v.y *= inv; v.z *= inv; v.w *= inv;
                *(float4*)(orow + lane * 4 + i * 128) = v;
            }
        }
    }

    // ---- Phase 3: O = (exp S) @ V, warp w takes k-rows [c*64+w*8, +8) ----
    float oc[8][4];
#pragma unroll
    for (int nt = 0; nt < 8; ++nt)
#pragma unroll
        for (int i = 0; i < 4; ++i) oc[nt][i] = 0.f;

#pragma unroll
    for (int j = 0; j < 4; ++j)
        pf[j] = *(const float4*)(Vb + (size_t)(lrow0 + j * 16) * DH + lc4);
#pragma unroll
    for (int j = 0; j < 4; ++j) {
        uint4 u = make_uint4(f2tf(pf[j].x), f2tf(pf[j].y), f2tf(pf[j].z), f2tf(pf[j].w));
        *(uint4*)(KV + (lrow0 + j * 16) * 68 + lc4) = u;
    }
    __syncthreads();

    for (int c = 0; c < 32; ++c) {
        const int buf = c & 1;
        if (c < 31) {
#pragma unroll
            for (int j = 0; j < 4; ++j)
                pf[j] = *(const float4*)(Vb + (size_t)((c + 1) * 64 + lrow0 + j * 16) * DH + lc4);
        }
        const uint32_t* Vc = KV + buf * (64 * 68);
        const int kw = c * 64 + w * 8;
        uint32_t a[4];
        a[0] = __float_as_uint(Ssm[g * S_STRIDE + kw + t]);
        a[1] = __float_as_uint(Ssm[(g + 8) * S_STRIDE + kw + t]);
        a[2] = __float_as_uint(Ssm[g * S_STRIDE + kw + t + 4]);
        a[3] = __float_as_uint(Ssm[(g + 8) * S_STRIDE + kw + t + 4]);
#pragma unroll
        for (int nt = 0; nt < 8; ++nt) {
            uint32_t b[2];
            b[0] = Vc[(w * 8 + t) * 68 + nt * 8 + g];
            b[1] = Vc[(w * 8 + t + 4) * 68 + nt * 8 + g];
            mma8(oc[nt], a, b);
        }
        if (c < 31) {
            uint32_t* Vn = KV + (buf ^ 1) * (64 * 68);
#pragma unroll
            for (int j = 0; j < 4; ++j) {
                uint4 u = make_uint4(f2tf(pf[j].x), f2tf(pf[j].y), f2tf(pf[j].z), f2tf(pf[j].w));
                *(uint4*)(Vn + (lrow0 + j * 16) * 68 + lc4) = u;
            }
        }
        __syncthreads();
    }

    // ---- cross-warp O reduction in SMEM (reuse KV region), scale, store ----
    float* Osm = (float*)KV;  // [8][16][68]
#pragma unroll
    for (int nt = 0; nt < 8; ++nt) {
        const int base = w * 1088 + nt * 8 + 2 * t;
        Osm[base + g * 68] = oc[nt][0];
        Osm[base + g * 68 + 1] = oc[nt][1];
        Osm[base + (g + 8) * 68] = oc[nt][2];
        Osm[base + (g + 8) * 68 + 1] = oc[nt][3];
    }
    __syncthreads();
    {
        const int m = tid >> 4;
        const int n4 = (tid & 15) * 4;
        float4 s = make_float4(0.f, 0.f, 0.f, 0.f);
#pragma unroll
        for (int ww = 0; ww < 8; ++ww) {
            float4 v = *(float4*)(Osm + ww * 1088 + m * 68 + n4);
            s.x += v.x; s.y += v.y; s.z += v.z; s.w += v.w;
        }
        const float inv = Rsum[m];
        s.x *= inv; s.y *= inv; s.z *= inv; s.w *= inv;
        const int b_ = bh >> 4;  // NH == 16
        const int h = bh & 15;
        *(float4*)(g_O + ((size_t)(m0 + m) * BATCH + b_) * EMB + h * 64 + n4) = s;
    }
}

// ---------------------------------------------------------------------------
// Launch
// ---------------------------------------------------------------------------
extern "C" void kernel_launch(void* const* d_in, const int* in_sizes, int n_in,
                              void* d_out, int out_size)
{
    const float* query = (const float*)d_in[0];
    const float* key   = (const float*)d_in[1];
    const float* value = (const float*)d_in[2];
    const float* Wq    = (const float*)d_in[3];
    const float* Wk    = (const float*)d_in[4];
    const float* Wv    = (const float*)d_in[5];
    const float* Wo    = (const float*)d_in[6];
    const float* bo    = (const float*)d_in[7];

    float* outp = (float*)d_out;
    float* attnp = nullptr;
    int attn_is_scratch = 0;
    int out_is_fb = 0;
    size_t osz = (size_t)out_size;
    if (osz >= OUT_ELEMS + ATTN_ELEMS) {
        attnp = (float*)d_out + OUT_ELEMS;
    } else if (osz == ATTN_ELEMS) {
        attnp = (float*)d_out;
        out_is_fb = 1;
    } else {
        attn_is_scratch = 1;
    }

    cudaFuncSetAttribute(fused_attn, cudaFuncAttributeMaxDynamicSharedMemorySize,
                         FUSED_SMEM);

    const float scale = 0.125f;  // DH^-0.5

    dim3 gProj(EMB / 128, MROWS / 128);  // (8, 32)
    gemm_tf32<0><<<gProj, 256>>>(query, Wq, nullptr, scale, nullptr, 0);
    gemm_tf32<1><<<gProj, 256>>>(key,   Wk, nullptr, 1.0f,  nullptr, 0);
    gemm_tf32<2><<<gProj, 256>>>(value, Wv, nullptr, 1.0f,  nullptr, 0);

    dim3 gF(SEQ / 16, BATCH * NH);  // (128, 32)
    fused_attn<<<gF, 256, FUSED_SMEM>>>(attnp, attn_is_scratch);

    gemm_tf32<3><<<gProj, 256>>>(nullptr, Wo, bo, 1.0f, outp, out_is_fb);
}